// round 12
// baseline (speedup 1.0000x reference)
#include <cuda_runtime.h>
#include <cstdint>

#define G    8
#define CG   32
#define CH   256
#define HWP  16384
#define TPB  256
#define PT   64
#define NT   4096
#define SROW 9          // stats stride per pixel, in ull (conflict padding)

typedef unsigned long long ull;

__device__ __forceinline__ ull pack2(float a, float b) {
    ull r; asm("mov.b64 %0, {%1,%2};" : "=l"(r) : "f"(a), "f"(b)); return r;
}
__device__ __forceinline__ void unpack2(ull v, float& a, float& b) {
    asm("mov.b64 {%0,%1}, %2;" : "=f"(a), "=f"(b) : "l"(v));
}
__device__ __forceinline__ void fma2(ull& d, ull a, ull b) {
    asm("fma.rn.f32x2 %0, %1, %2, %0;" : "+l"(d) : "l"(a), "l"(b));
}

#define NEG_INF __int_as_float(0xff800000)

__global__ void __launch_bounds__(TPB, 2)
cgblock_kernel(const float* __restrict__ x,
               const float* __restrict__ soft_w1,
               const float* __restrict__ soft_w2,
               const float* __restrict__ top_w1,
               const float* __restrict__ top_w2,
               const float* __restrict__ rr,
               float* __restrict__ out)
{
    __shared__ __align__(16) ull  s_w2[CH * 8];       // (ws,wt) pairs per (o,g): 16KB
    __shared__ __align__(16) ull  s_st[2][PT * SROW]; // stats (sv,tv) per px,g: 2x4.5KB
    __shared__ float s_w1[G * CG];
    __shared__ float s_tw1[G * 4];

    const int tid  = threadIdx.x;
    const int warp = tid >> 5;
    const int lane = tid & 31;

    // ---- one-time weight prep: s_w2[o*8+g] = (rs*soft_w2[o,g], rt*top_w2[o,g]) ----
    {
        float r0 = __ldg(rr), r1 = __ldg(rr + 1);
        float rm = fmaxf(r0, r1);
        float e0 = __expf(r0 - rm), e1 = __expf(r1 - rm);
        float inv = __frcp_rn(e0 + e1);
        float w_top = e0 * inv, w_soft = e1 * inv;
        #pragma unroll
        for (int i = tid; i < CH * G; i += TPB) {
            int o = i >> 3, g = i & 7;
            s_w2[i] = pack2(w_soft * __ldg(soft_w2 + o * G + g),
                            w_top  * __ldg(top_w2  + o * G + g));
        }
        #pragma unroll
        for (int i = tid; i < G * CG; i += TPB) s_w1[i] = __ldg(soft_w1 + i);
        if (tid < G * 4) s_tw1[tid] = __ldg(top_w1 + tid);
    }
    __syncthreads();

    const int S = gridDim.x;
    int i = 0;
    for (int t = blockIdx.x; t < NT; t += S, i++) {
        const int sb = i & 1;
        const int p  = t * PT;
        const int b  = p >> 14;
        const int sp = p & (HWP - 1);

        // ---------- Phase 1: thread = (g, px-pair). LDG (caching) -> warms L1. ----
        {
            const int g  = tid >> 5;      // 0..7
            const int pp = tid & 31;      // 0..31
            const int px = 2 * pp;
            const float* xg  = x + ((size_t)b * CH + g * CG) * HWP + sp + px;
            const float* w1p = s_w1 + g * CG;

            // 4 independent chains: (even/odd channel) x (px0/px1)
            float esA = 0.f, ysA = 0.f, esB = 0.f, ysB = 0.f;
            float esC = 0.f, ysC = 0.f, esD = 0.f, ysD = 0.f;
            float aA = NEG_INF, bA = NEG_INF, cA = NEG_INF, dA = NEG_INF;
            float aB = NEG_INF, bB = NEG_INF, cB = NEG_INF, dB = NEG_INF;
            float aC = NEG_INF, bC = NEG_INF, cC = NEG_INF, dC = NEG_INF;
            float aD = NEG_INF, bD = NEG_INF, cD = NEG_INF, dD = NEG_INF;

            #pragma unroll
            for (int c = 0; c < 16; c++) {
                float2 v0 = *(const float2*)(xg + (size_t)(2 * c) * HWP);
                float2 v1 = *(const float2*)(xg + (size_t)(2 * c + 1) * HWP);
                float w0 = w1p[2 * c], w1 = w1p[2 * c + 1];
                { // chain A: even c, px0
                    float v = v0.x, e = __expf(v); esA += e; ysA = fmaf(v * e, w0, ysA);
                    float f = fminf(aA, v); aA = fmaxf(aA, v);
                    float h = fminf(bA, f); bA = fmaxf(bA, f);
                    float j = fminf(cA, h); cA = fmaxf(cA, h);
                    dA = fmaxf(dA, j);
                }
                { // chain B: even c, px1
                    float v = v0.y, e = __expf(v); esB += e; ysB = fmaf(v * e, w0, ysB);
                    float f = fminf(aB, v); aB = fmaxf(aB, v);
                    float h = fminf(bB, f); bB = fmaxf(bB, f);
                    float j = fminf(cB, h); cB = fmaxf(cB, h);
                    dB = fmaxf(dB, j);
                }
                { // chain C: odd c, px0
                    float v = v1.x, e = __expf(v); esC += e; ysC = fmaf(v * e, w1, ysC);
                    float f = fminf(aC, v); aC = fmaxf(aC, v);
                    float h = fminf(bC, f); bC = fmaxf(bC, f);
                    float j = fminf(cC, h); cC = fmaxf(cC, h);
                    dC = fmaxf(dC, j);
                }
                { // chain D: odd c, px1
                    float v = v1.y, e = __expf(v); esD += e; ysD = fmaf(v * e, w1, ysD);
                    float f = fminf(aD, v); aD = fmaxf(aD, v);
                    float h = fminf(bD, f); bD = fmaxf(bD, f);
                    float j = fminf(cD, h); cD = fmaxf(cD, h);
                    dD = fmaxf(dD, j);
                }
            }
            float k0 = s_tw1[g * 4 + 0], k1 = s_tw1[g * 4 + 1];
            float k2 = s_tw1[g * 4 + 2], k3 = s_tw1[g * 4 + 3];

            // px0: merge A & C (bitonic top-4 of two sorted quads)
            {
                float m1 = fmaxf(aA, dC), m2 = fmaxf(bA, cC);
                float m3 = fmaxf(cA, bC), m4 = fmaxf(dA, aC);
                float q1 = fmaxf(m1, m3), q3 = fminf(m1, m3);
                float q2 = fmaxf(m2, m4), q4 = fminf(m2, m4);
                float A = fmaxf(q1, q2), B = fminf(q1, q2);
                float C = fmaxf(q3, q4), D = fminf(q3, q4);
                float sv = __fdividef(ysA + ysC, esA + esC);
                float tv = fmaf(A, k0, fmaf(B, k1, fmaf(C, k2, D * k3)));
                s_st[sb][px * SROW + g] = pack2(sv, tv);
            }
            // px1: merge B & D
            {
                float m1 = fmaxf(aB, dD), m2 = fmaxf(bB, cD);
                float m3 = fmaxf(cB, bD), m4 = fmaxf(dB, aD);
                float q1 = fmaxf(m1, m3), q3 = fminf(m1, m3);
                float q2 = fmaxf(m2, m4), q4 = fminf(m2, m4);
                float A = fmaxf(q1, q2), B = fminf(q1, q2);
                float C = fmaxf(q3, q4), D = fminf(q3, q4);
                float sv = __fdividef(ysB + ysD, esB + esD);
                float tv = fmaf(A, k0, fmaf(B, k1, fmaf(C, k2, D * k3)));
                s_st[sb][(px + 1) * SROW + g] = pack2(sv, tv);
            }
        }
        __syncthreads();   // stats(t) ready; the ONLY barrier per tile

        // ---------- Phase 2: warp -> 32 channels; lane -> pixel pair. x from L1. ----
        {
            const int px0 = 2 * lane;
            ull st0[8], st1[8];
            #pragma unroll
            for (int g2 = 0; g2 < 8; g2++) {
                st0[g2] = s_st[sb][px0 * SROW + g2];
                st1[g2] = s_st[sb][(px0 + 1) * SROW + g2];
            }
            const float* xb = x   + (size_t)b * CH * HWP + sp;
            float*       ob = out + (size_t)b * CH * HWP + sp;
            const int cb = warp * 32;
            #pragma unroll 4
            for (int ii = 0; ii < 32; ii++) {
                int o = cb + ii;
                float2 xv = *(const float2*)(xb + (size_t)o * HWP + px0);  // L1 hit
                ull acc0 = pack2(xv.x, 0.f);
                ull acc1 = pack2(xv.y, 0.f);
                const ulonglong2* wo = (const ulonglong2*)(s_w2 + o * 8);
                #pragma unroll
                for (int gg = 0; gg < 4; gg++) {
                    ulonglong2 wv = wo[gg];
                    fma2(acc0, st0[2 * gg],     wv.x);
                    fma2(acc1, st1[2 * gg],     wv.x);
                    fma2(acc0, st0[2 * gg + 1], wv.y);
                    fma2(acc1, st1[2 * gg + 1], wv.y);
                }
                float lo0, hi0, lo1, hi1;
                unpack2(acc0, lo0, hi0);
                unpack2(acc1, lo1, hi1);
                __stcs((float2*)(ob + (size_t)o * HWP + px0),
                       make_float2(lo0 + hi0, lo1 + hi1));
            }
        }
        // no trailing barrier: stats are double-buffered; sb reused only at t+2,
        // which is ordered behind next iteration's __syncthreads.
    }
}

extern "C" void kernel_launch(void* const* d_in, const int* in_sizes, int n_in,
                              void* d_out, int out_size) {
    const float* x   = (const float*)d_in[0];
    const float* sw1 = (const float*)d_in[1];
    const float* sw2 = (const float*)d_in[2];
    const float* tw1 = (const float*)d_in[3];
    const float* tw2 = (const float*)d_in[4];
    const float* r   = (const float*)d_in[5];
    float* out = (float*)d_out;

    static int sms = 0;
    if (sms == 0) cudaDeviceGetAttribute(&sms, cudaDevAttrMultiProcessorCount, 0);

    cgblock_kernel<<<2 * sms, TPB>>>(x, sw1, sw2, tw1, tw2, r, out);
}

// round 13
// speedup vs baseline: 1.0226x; 1.0226x over previous
#include <cuda_runtime.h>
#include <cstdint>

#define G    8
#define CG   32
#define CH   256
#define HWP  16384
#define TPB  256
#define PT   64
#define NT   4096
#define SROW 9          // stats stride per pixel, in ull (conflict padding)

typedef unsigned long long ull;

__device__ __forceinline__ ull pack2(float a, float b) {
    ull r; asm("mov.b64 %0, {%1,%2};" : "=l"(r) : "f"(a), "f"(b)); return r;
}
__device__ __forceinline__ void unpack2(ull v, float& a, float& b) {
    asm("mov.b64 {%0,%1}, %2;" : "=f"(a), "=f"(b) : "l"(v));
}
__device__ __forceinline__ void fma2(ull& d, ull a, ull b) {
    asm("fma.rn.f32x2 %0, %1, %2, %0;" : "+l"(d) : "l"(a), "l"(b));
}

#define NEG_INF __int_as_float(0xff800000)

__global__ void __launch_bounds__(TPB, 3)
cgblock_kernel(const float* __restrict__ x,
               const float* __restrict__ soft_w1,
               const float* __restrict__ soft_w2,
               const float* __restrict__ top_w1,
               const float* __restrict__ top_w2,
               const float* __restrict__ rr,
               float* __restrict__ out)
{
    __shared__ __align__(16) ull  s_w2[CH * 8];       // (ws,wt) pairs per (o,g): 16KB
    __shared__ __align__(16) ull  s_st[2][PT * SROW]; // stats (sv,tv) per px,g: 2x4.5KB
    __shared__ float s_w1[G * CG];
    __shared__ float s_tw1[G * 4];

    const int tid  = threadIdx.x;
    const int warp = tid >> 5;
    const int lane = tid & 31;

    // ---- one-time weight prep: s_w2[o*8+g] = (rs*soft_w2[o,g], rt*top_w2[o,g]) ----
    {
        float r0 = __ldg(rr), r1 = __ldg(rr + 1);
        float rm = fmaxf(r0, r1);
        float e0 = __expf(r0 - rm), e1 = __expf(r1 - rm);
        float inv = __frcp_rn(e0 + e1);
        float w_top = e0 * inv, w_soft = e1 * inv;
        #pragma unroll
        for (int i = tid; i < CH * G; i += TPB) {
            int o = i >> 3, g = i & 7;
            s_w2[i] = pack2(w_soft * __ldg(soft_w2 + o * G + g),
                            w_top  * __ldg(top_w2  + o * G + g));
        }
        #pragma unroll
        for (int i = tid; i < G * CG; i += TPB) s_w1[i] = __ldg(soft_w1 + i);
        if (tid < G * 4) s_tw1[tid] = __ldg(top_w1 + tid);
    }
    __syncthreads();

    const int S = gridDim.x;
    int i = 0;
    for (int t = blockIdx.x; t < NT; t += S, i++) {
        const int sb = i & 1;
        const int p  = t * PT;
        const int b  = p >> 14;
        const int sp = p & (HWP - 1);

        // ---------- Phase 1: thread = (g, px-pair). One chain per pixel. ----------
        {
            const int g  = tid >> 5;      // 0..7
            const int pp = tid & 31;      // 0..31
            const int px = 2 * pp;
            const float* xg  = x + ((size_t)b * CH + g * CG) * HWP + sp + px;
            const float* w1p = s_w1 + g * CG;

            float es0 = 0.f, ys0 = 0.f, es1 = 0.f, ys1 = 0.f;
            float a0 = NEG_INF, b0 = NEG_INF, c0 = NEG_INF, d0 = NEG_INF;
            float a1 = NEG_INF, b1 = NEG_INF, c1 = NEG_INF, d1 = NEG_INF;

            #pragma unroll 8
            for (int c = 0; c < CG; c++) {
                float2 v = *(const float2*)(xg + (size_t)c * HWP);
                float w1 = w1p[c];
                {
                    float vv = v.x, e = __expf(vv);
                    es0 += e; ys0 = fmaf(vv * e, w1, ys0);
                    float f = fminf(a0, vv); a0 = fmaxf(a0, vv);
                    float h = fminf(b0, f);  b0 = fmaxf(b0, f);
                    float j = fminf(c0, h);  c0 = fmaxf(c0, h);
                    d0 = fmaxf(d0, j);
                }
                {
                    float vv = v.y, e = __expf(vv);
                    es1 += e; ys1 = fmaf(vv * e, w1, ys1);
                    float f = fminf(a1, vv); a1 = fmaxf(a1, vv);
                    float h = fminf(b1, f);  b1 = fmaxf(b1, f);
                    float j = fminf(c1, h);  c1 = fmaxf(c1, h);
                    d1 = fmaxf(d1, j);
                }
            }
            float k0 = s_tw1[g * 4 + 0], k1 = s_tw1[g * 4 + 1];
            float k2 = s_tw1[g * 4 + 2], k3 = s_tw1[g * 4 + 3];

            s_st[sb][px * SROW + g] =
                pack2(__fdividef(ys0, es0),
                      fmaf(a0, k0, fmaf(b0, k1, fmaf(c0, k2, d0 * k3))));
            s_st[sb][(px + 1) * SROW + g] =
                pack2(__fdividef(ys1, es1),
                      fmaf(a1, k0, fmaf(b1, k1, fmaf(c1, k2, d1 * k3))));
        }
        __syncthreads();   // stats(t) ready; the ONLY barrier per tile

        // ---------- Phase 2: warp -> 32 channels; lane -> pixel pair. ----------
        {
            const int px0 = 2 * lane;
            ull st0[8], st1[8];
            #pragma unroll
            for (int g2 = 0; g2 < 8; g2++) {
                st0[g2] = s_st[sb][px0 * SROW + g2];
                st1[g2] = s_st[sb][(px0 + 1) * SROW + g2];
            }
            const float* xb = x   + (size_t)b * CH * HWP + sp;
            float*       ob = out + (size_t)b * CH * HWP + sp;
            const int cb = warp * 32;
            #pragma unroll 4
            for (int ii = 0; ii < 32; ii++) {
                int o = cb + ii;
                float2 xv = *(const float2*)(xb + (size_t)o * HWP + px0);  // L1/L2 hit
                ull acc0 = pack2(xv.x, 0.f);
                ull acc1 = pack2(xv.y, 0.f);
                const ulonglong2* wo = (const ulonglong2*)(s_w2 + o * 8);
                #pragma unroll
                for (int gg = 0; gg < 4; gg++) {
                    ulonglong2 wv = wo[gg];
                    fma2(acc0, st0[2 * gg],     wv.x);
                    fma2(acc1, st1[2 * gg],     wv.x);
                    fma2(acc0, st0[2 * gg + 1], wv.y);
                    fma2(acc1, st1[2 * gg + 1], wv.y);
                }
                float lo0, hi0, lo1, hi1;
                unpack2(acc0, lo0, hi0);
                unpack2(acc1, lo1, hi1);
                __stcs((float2*)(ob + (size_t)o * HWP + px0),
                       make_float2(lo0 + hi0, lo1 + hi1));
            }
        }
        // no trailing barrier: stats double-buffered; sb reused only at t+2,
        // ordered behind next iteration's __syncthreads.
    }
}

extern "C" void kernel_launch(void* const* d_in, const int* in_sizes, int n_in,
                              void* d_out, int out_size) {
    const float* x   = (const float*)d_in[0];
    const float* sw1 = (const float*)d_in[1];
    const float* sw2 = (const float*)d_in[2];
    const float* tw1 = (const float*)d_in[3];
    const float* tw2 = (const float*)d_in[4];
    const float* r   = (const float*)d_in[5];
    float* out = (float*)d_out;

    static int sms = 0;
    if (sms == 0) cudaDeviceGetAttribute(&sms, cudaDevAttrMultiProcessorCount, 0);

    cgblock_kernel<<<3 * sms, TPB>>>(x, sw1, sw2, tw1, tw2, r, out);
}

// round 14
// speedup vs baseline: 1.1535x; 1.1279x over previous
#include <cuda_runtime.h>
#include <cstdint>

#define G    8
#define CG   32
#define CH   256
#define HWP  16384
#define TPB  256
#define PT   64
#define NT   4096

typedef unsigned long long ull;

__device__ __forceinline__ ull pack2(float a, float b) {
    ull r; asm("mov.b64 %0, {%1,%2};" : "=l"(r) : "f"(a), "f"(b)); return r;
}
__device__ __forceinline__ void unpack2(ull v, float& a, float& b) {
    asm("mov.b64 {%0,%1}, %2;" : "=f"(a), "=f"(b) : "l"(v));
}
__device__ __forceinline__ void fma2(ull& d, ull a, ull b) {
    asm("fma.rn.f32x2 %0, %1, %2, %0;" : "+l"(d) : "l"(a), "l"(b));
}

#define NEG_INF __int_as_float(0xff800000)

// sort 4 floats descending: a>=b>=c>=d (10 ops)
__device__ __forceinline__ void sort4(float w, float x, float y, float z,
                                      float& a, float& b, float& c, float& d) {
    float h1 = fmaxf(w, x), l1 = fminf(w, x);
    float h2 = fmaxf(y, z), l2 = fminf(y, z);
    a = fmaxf(h1, h2); float t = fminf(h1, h2);
    d = fminf(l1, l2); float u = fmaxf(l1, l2);
    b = fmaxf(t, u);  c = fminf(t, u);
}

// top4(A ∪ P), both sorted descending (12 ops; bitonic cleanup — R10/R11 validated)
__device__ __forceinline__ void merge4(float& a, float& b, float& c, float& d,
                                       float p, float q, float r, float s) {
    float m1 = fmaxf(a, s), m2 = fmaxf(b, r);
    float m3 = fmaxf(c, q), m4 = fmaxf(d, p);
    float r1 = fmaxf(m1, m3), r3 = fminf(m1, m3);
    float r2 = fmaxf(m2, m4), r4 = fminf(m2, m4);
    a = fmaxf(r1, r2); b = fminf(r1, r2);
    c = fmaxf(r3, r4); d = fminf(r3, r4);
}

__global__ void __launch_bounds__(TPB, 3)
cgblock_kernel(const float* __restrict__ x,
               const float* __restrict__ soft_w1,
               const float* __restrict__ soft_w2,
               const float* __restrict__ top_w1,
               const float* __restrict__ top_w2,
               const float* __restrict__ rr,
               float* __restrict__ out)
{
    __shared__ __align__(16) ull s_w2[CH * 8];      // (ws,wt) per (o,g): 16KB
    __shared__ __align__(16) ull s_st[2][G][PT];    // stats (sv,tv): [buf][g][px], 8KB
    __shared__ float s_w1[G * CG];
    __shared__ float s_tw1[G * 4];

    const int tid  = threadIdx.x;
    const int warp = tid >> 5;
    const int lane = tid & 31;

    // ---- one-time weight prep: s_w2[o*8+g] = (rs*soft_w2[o,g], rt*top_w2[o,g]) ----
    {
        float r0 = __ldg(rr), r1 = __ldg(rr + 1);
        float rm = fmaxf(r0, r1);
        float e0 = __expf(r0 - rm), e1 = __expf(r1 - rm);
        float inv = __frcp_rn(e0 + e1);
        float w_top = e0 * inv, w_soft = e1 * inv;
        #pragma unroll
        for (int i = tid; i < CH * G; i += TPB) {
            int o = i >> 3, g = i & 7;
            s_w2[i] = pack2(w_soft * __ldg(soft_w2 + o * G + g),
                            w_top  * __ldg(top_w2  + o * G + g));
        }
        #pragma unroll
        for (int i = tid; i < G * CG; i += TPB) s_w1[i] = __ldg(soft_w1 + i);
        if (tid < G * 4) s_tw1[tid] = __ldg(top_w1 + tid);
    }
    __syncthreads();

    const int S = gridDim.x;
    int it = 0;
    for (int t = blockIdx.x; t < NT; t += S, it++) {
        const int sb = it & 1;
        const int p  = t * PT;
        const int b  = p >> 14;
        const int sp = p & (HWP - 1);

        // ---------- Phase 1: thread = (g, px-pair); channels in sorted-4 batches ----
        {
            const int g  = warp;          // 0..7 (one warp per group)
            const int px = 2 * lane;
            const float* xg  = x + ((size_t)b * CH + g * CG) * HWP + sp + px;
            const float* w1p = s_w1 + g * CG;

            float es0 = 0.f, ys0 = 0.f, es1 = 0.f, ys1 = 0.f;
            float a0, b0, c0, d0, a1, b1, c1, d1;

            // batch 0: initializes the sorted accumulators directly
            {
                float2 v0 = *(const float2*)(xg + 0 * (size_t)HWP);
                float2 v1 = *(const float2*)(xg + 1 * (size_t)HWP);
                float2 v2 = *(const float2*)(xg + 2 * (size_t)HWP);
                float2 v3 = *(const float2*)(xg + 3 * (size_t)HWP);
                float w0 = w1p[0], w1 = w1p[1], w2 = w1p[2], w3 = w1p[3];
                float e;
                e = __expf(v0.x); es0 += e; ys0 = fmaf(v0.x * e, w0, ys0);
                e = __expf(v1.x); es0 += e; ys0 = fmaf(v1.x * e, w1, ys0);
                e = __expf(v2.x); es0 += e; ys0 = fmaf(v2.x * e, w2, ys0);
                e = __expf(v3.x); es0 += e; ys0 = fmaf(v3.x * e, w3, ys0);
                e = __expf(v0.y); es1 += e; ys1 = fmaf(v0.y * e, w0, ys1);
                e = __expf(v1.y); es1 += e; ys1 = fmaf(v1.y * e, w1, ys1);
                e = __expf(v2.y); es1 += e; ys1 = fmaf(v2.y * e, w2, ys1);
                e = __expf(v3.y); es1 += e; ys1 = fmaf(v3.y * e, w3, ys1);
                sort4(v0.x, v1.x, v2.x, v3.x, a0, b0, c0, d0);
                sort4(v0.y, v1.y, v2.y, v3.y, a1, b1, c1, d1);
            }

            #pragma unroll
            for (int bt = 1; bt < 8; bt++) {
                const float* xc = xg + (size_t)(4 * bt) * HWP;
                float2 v0 = *(const float2*)(xc + 0 * (size_t)HWP);
                float2 v1 = *(const float2*)(xc + 1 * (size_t)HWP);
                float2 v2 = *(const float2*)(xc + 2 * (size_t)HWP);
                float2 v3 = *(const float2*)(xc + 3 * (size_t)HWP);
                float w0 = w1p[4 * bt], w1 = w1p[4 * bt + 1];
                float w2 = w1p[4 * bt + 2], w3 = w1p[4 * bt + 3];
                float e;
                e = __expf(v0.x); es0 += e; ys0 = fmaf(v0.x * e, w0, ys0);
                e = __expf(v1.x); es0 += e; ys0 = fmaf(v1.x * e, w1, ys0);
                e = __expf(v2.x); es0 += e; ys0 = fmaf(v2.x * e, w2, ys0);
                e = __expf(v3.x); es0 += e; ys0 = fmaf(v3.x * e, w3, ys0);
                e = __expf(v0.y); es1 += e; ys1 = fmaf(v0.y * e, w0, ys1);
                e = __expf(v1.y); es1 += e; ys1 = fmaf(v1.y * e, w1, ys1);
                e = __expf(v2.y); es1 += e; ys1 = fmaf(v2.y * e, w2, ys1);
                e = __expf(v3.y); es1 += e; ys1 = fmaf(v3.y * e, w3, ys1);
                float sa, sbv, sc, sd;
                sort4(v0.x, v1.x, v2.x, v3.x, sa, sbv, sc, sd);
                merge4(a0, b0, c0, d0, sa, sbv, sc, sd);
                sort4(v0.y, v1.y, v2.y, v3.y, sa, sbv, sc, sd);
                merge4(a1, b1, c1, d1, sa, sbv, sc, sd);
            }

            float k0 = s_tw1[g * 4 + 0], k1 = s_tw1[g * 4 + 1];
            float k2 = s_tw1[g * 4 + 2], k3 = s_tw1[g * 4 + 3];
            ulonglong2 st2;
            st2.x = pack2(__fdividef(ys0, es0),
                          fmaf(a0, k0, fmaf(b0, k1, fmaf(c0, k2, d0 * k3))));
            st2.y = pack2(__fdividef(ys1, es1),
                          fmaf(a1, k0, fmaf(b1, k1, fmaf(c1, k2, d1 * k3))));
            *(ulonglong2*)&s_st[sb][g][px] = st2;   // STS.128, conflict-free
        }
        __syncthreads();   // stats(t) ready; the ONLY barrier per tile

        // ---------- Phase 2: warp -> 32 channels; lane -> pixel pair ----------
        {
            const int px0 = 2 * lane;
            ull st0[8], st1[8];
            #pragma unroll
            for (int g2 = 0; g2 < 8; g2++) {
                ulonglong2 v = *(const ulonglong2*)&s_st[sb][g2][px0];  // LDS.128
                st0[g2] = v.x;
                st1[g2] = v.y;
            }
            const float* xb = x   + (size_t)b * CH * HWP + sp;
            float*       ob = out + (size_t)b * CH * HWP + sp;
            const int cb = warp * 32;
            #pragma unroll 4
            for (int ii = 0; ii < 32; ii++) {
                int o = cb + ii;
                float2 xv = *(const float2*)(xb + (size_t)o * HWP + px0);  // L1/L2 hit
                ull acc0 = pack2(xv.x, 0.f);
                ull acc1 = pack2(xv.y, 0.f);
                const ulonglong2* wo = (const ulonglong2*)(s_w2 + o * 8);
                #pragma unroll
                for (int gg = 0; gg < 4; gg++) {
                    ulonglong2 wv = wo[gg];
                    fma2(acc0, st0[2 * gg],     wv.x);
                    fma2(acc1, st1[2 * gg],     wv.x);
                    fma2(acc0, st0[2 * gg + 1], wv.y);
                    fma2(acc1, st1[2 * gg + 1], wv.y);
                }
                float lo0, hi0, lo1, hi1;
                unpack2(acc0, lo0, hi0);
                unpack2(acc1, lo1, hi1);
                __stcs((float2*)(ob + (size_t)o * HWP + px0),
                       make_float2(lo0 + hi0, lo1 + hi1));
            }
        }
        // no trailing barrier: stats double-buffered; buffer sb reused at t+2,
        // ordered behind the next iteration's __syncthreads.
    }
}

extern "C" void kernel_launch(void* const* d_in, const int* in_sizes, int n_in,
                              void* d_out, int out_size) {
    const float* x   = (const float*)d_in[0];
    const float* sw1 = (const float*)d_in[1];
    const float* sw2 = (const float*)d_in[2];
    const float* tw1 = (const float*)d_in[3];
    const float* tw2 = (const float*)d_in[4];
    const float* r   = (const float*)d_in[5];
    float* out = (float*)d_out;

    static int sms = 0;
    if (sms == 0) cudaDeviceGetAttribute(&sms, cudaDevAttrMultiProcessorCount, 0);

    cgblock_kernel<<<3 * sms, TPB>>>(x, sw1, sw2, tw1, tw2, r, out);
}